// round 7
// baseline (speedup 1.0000x reference)
#include <cuda_runtime.h>
#include <cuda_bf16.h>
#include <math.h>
#include <stdint.h>

#define B_ 64
#define C_ 256
#define T_ 32
#define HW_ 49
#define N_ 1568      // T_*HW_
#define KV_ 97
#define KN_ 300
#define D_ 512
#define NTOK_ 392
#define MROWS (B_ * N_)          // 100352 = 784 * 128
#define NBT (B_ * T_)            // 2048 t-slices

// ---------------- scratch (device globals: allocation-free) ----------------
__device__ float g_cam[MROWS];
__device__ __nv_bfloat16 g_xT[(size_t)NBT * HW_ * C_];        // [bt][pos][c]
__device__ __nv_bfloat16 g_W[9 * D_ * C_];                    // [tap][d][c]
__device__ float g_loss;

// ---------------- helpers ----------------
__device__ __forceinline__ void mma16816(float* c, const uint32_t* a,
                                         uint32_t b0, uint32_t b1) {
    asm volatile(
        "mma.sync.aligned.m16n8k16.row.col.f32.bf16.bf16.f32 "
        "{%0,%1,%2,%3}, {%4,%5,%6,%7}, {%8,%9}, {%0,%1,%2,%3};\n"
        : "+f"(c[0]), "+f"(c[1]), "+f"(c[2]), "+f"(c[3])
        : "r"(a[0]), "r"(a[1]), "r"(a[2]), "r"(a[3]), "r"(b0), "r"(b1));
}
__device__ __forceinline__ void ldsm_x4(uint32_t* r, uint32_t addr) {
    asm volatile("ldmatrix.sync.aligned.m8n8.x4.shared.b16 {%0,%1,%2,%3}, [%4];"
                 : "=r"(r[0]), "=r"(r[1]), "=r"(r[2]), "=r"(r[3]) : "r"(addr));
}
__device__ __forceinline__ void cp_async16(uint32_t s, const void* g) {
    asm volatile("cp.async.cg.shared.global [%0], [%1], 16;\n" :: "r"(s), "l"(g));
}
__device__ __forceinline__ void cp_commit() { asm volatile("cp.async.commit_group;\n"); }
__device__ __forceinline__ uint32_t smem_u32(const void* p) {
    uint32_t a;
    asm("{ .reg .u64 t; cvta.to.shared.u64 t, %1; cvt.u32.u64 %0, t; }" : "=r"(a) : "l"(p));
    return a;
}

// ---------------- kernel: weight transpose  conv_w(D,C,1,3,3) -> g_W[tap][d][c]
__global__ void prep_w_kernel(const float* __restrict__ conv_w) {
    int idx = blockIdx.x * blockDim.x + threadIdx.x;
    const int total = 9 * D_ * C_;
    if (idx >= total) return;
    int c = idx % C_;
    int d = (idx / C_) % D_;
    int tap = idx / (C_ * D_);
    g_W[idx] = __float2bfloat16(conv_w[(d * C_ + c) * 9 + tap]);
}

// ---------------- kernel: x transpose  x(B,C,T,HW) -> g_xT[bt][pos][c] bf16
__global__ void prep_x_kernel(const float* __restrict__ x) {
    __shared__ __nv_bfloat16 sm[C_ * HW_];
    int bt = blockIdx.x;
    int b = bt / T_, t = bt % T_;
    const float* src = x + (size_t)b * C_ * N_ + (size_t)t * HW_;
    for (int i = threadIdx.x; i < C_ * HW_; i += 256) {
        int c = i / HW_, p = i % HW_;
        sm[i] = __float2bfloat16(src[(size_t)c * N_ + p]);
    }
    __syncthreads();
    __nv_bfloat16* dst = g_xT + (size_t)bt * HW_ * C_;
    for (int i = threadIdx.x; i < C_ * HW_; i += 256) {
        int p = i / C_, c = i % C_;
        dst[i] = sm[c * HW_ + p];
    }
}

// ---------------- kernel: CAM (one block per sample) ----------------
__global__ void cam_kernel(const float* __restrict__ x,
                           const float* __restrict__ lv, const float* __restrict__ ln,
                           const float* __restrict__ wpv, const float* __restrict__ wpn) {
    __shared__ float w_v[C_], w_n[C_];
    __shared__ float rv[N_], rn[N_];
    __shared__ float sbuf[2048];
    __shared__ float red[256];
    __shared__ int redi[256];
    __shared__ float thrs[2];

    int b = blockIdx.x;
    int tid = threadIdx.x;

    for (int br = 0; br < 2; ++br) {
        const float* lg = br ? ln : lv;
        int K = br ? KN_ : KV_;
        const float* wp = br ? wpn : wpv;
        float best = -INFINITY; int bi = 0x7fffffff;
        for (int i = tid; i < K; i += 256) {
            float v = lg[b * K + i];
            if (v > best || (v == best && i < bi)) { best = v; bi = i; }
        }
        red[tid] = best; redi[tid] = bi;
        __syncthreads();
        for (int s = 128; s > 0; s >>= 1) {
            if (tid < s) {
                float ov = red[tid + s]; int oi = redi[tid + s];
                if (ov > red[tid] || (ov == red[tid] && oi < redi[tid])) {
                    red[tid] = ov; redi[tid] = oi;
                }
            }
            __syncthreads();
        }
        int top = redi[0];
        __syncthreads();
        float* wdst = br ? w_n : w_v;
        wdst[tid] = wp[top * C_ + tid];
        __syncthreads();
    }

    const float* xb = x + (size_t)b * C_ * N_;
    float av[7], an[7];
#pragma unroll
    for (int i = 0; i < 7; ++i) { av[i] = 0.f; an[i] = 0.f; }
    for (int c = 0; c < C_; ++c) {
        float wv_ = w_v[c], wn_ = w_n[c];
        const float* xc = xb + (size_t)c * N_;
#pragma unroll
        for (int i = 0; i < 7; ++i) {
            int n = tid + i * 256;
            if (n < N_) {
                float xv = __ldg(xc + n);
                av[i] += wv_ * xv;
                an[i] += wn_ * xv;
            }
        }
    }
#pragma unroll
    for (int i = 0; i < 7; ++i) {
        int n = tid + i * 256;
        if (n < N_) { rv[n] = av[i]; rn[n] = an[i]; }
    }
    __syncthreads();

    for (int br = 0; br < 2; ++br) {
        float* r = br ? rn : rv;
        float mn = INFINITY, mx = -INFINITY;
        for (int n = tid; n < N_; n += 256) { float v = r[n]; mn = fminf(mn, v); mx = fmaxf(mx, v); }
        red[tid] = mn; sbuf[tid] = mx;
        __syncthreads();
        for (int s = 128; s > 0; s >>= 1) {
            if (tid < s) { red[tid] = fminf(red[tid], red[tid + s]); sbuf[tid] = fmaxf(sbuf[tid], sbuf[tid + s]); }
            __syncthreads();
        }
        mn = red[0]; mx = sbuf[0];
        __syncthreads();
        float inv = 1.0f / (mx - mn);
        for (int n = tid; n < N_; n += 256) r[n] = (r[n] - mn) * inv;
        __syncthreads();
        for (int i = tid; i < 2048; i += 256) sbuf[i] = (i < N_) ? r[i] : -INFINITY;
        __syncthreads();
        for (int k = 2; k <= 2048; k <<= 1) {
            for (int j = k >> 1; j > 0; j >>= 1) {
                for (int i = tid; i < 2048; i += 256) {
                    int ixj = i ^ j;
                    if (ixj > i) {
                        bool up = ((i & k) == 0);
                        float a0 = sbuf[i], b0 = sbuf[ixj];
                        if ((a0 > b0) == up) { sbuf[i] = b0; sbuf[ixj] = a0; }
                    }
                }
                __syncthreads();
            }
        }
        if (tid == 0) thrs[br] = sbuf[2048 - NTOK_];
        __syncthreads();
    }

    float tv = thrs[0], tn = thrs[1];
    for (int n = tid; n < N_; n += 256) {
        float a = rv[n]; a = (a >= tv) ? a : 0.0f;
        float c2 = rn[n]; c2 = (c2 >= tn) ? c2 : 0.0f;
        g_cam[b * N_ + n] = fmaxf(a, c2);
    }
}

// ---------------- loss init / finalize ----------------
__global__ void init_kernel() { g_loss = 0.0f; }
__global__ void final_kernel(float* out) { out[0] = g_loss * (1.0f / (float)MROWS); }

// ---------------- conv-GEMM + ReLU + score + BCE (global-row M-tiling) ------
// M = 128 consecutive global rows (all valid), N = 512 (4 x 128 d-tiles),
// K = 2304 in 144 pipeline stages of (d-tile, 64 channels).
#define XSTR 264                       // x row stride (bf16), 528 B
#define XROWS 197                      // 4 slices * 49 + zero row
#define XSM_BYTES (XROWS * XSTR * 2)   // 104016
#define WSM_OFF   104032
#define WSTR 72                        // w row stride (bf16), 144 B
#define WBUF (128 * WSTR * 2)          // 18432 per buffer
#define SROW_OFF  (WSM_OFF + 2 * WBUF) // 140896
#define SWSM_OFF  (SROW_OFF + 512)
#define CBSM_OFF  (SWSM_OFF + 2048)
#define REDB_OFF  (CBSM_OFF + 2048)
#define SMEM_GEMM (REDB_OFF + 64)

__global__ __launch_bounds__(256, 1)
void gemm_kernel(const float* __restrict__ conv_b,
                 const float* __restrict__ score_w,
                 const float* __restrict__ score_b) {
    extern __shared__ char smem[];
    uint32_t sbx = smem_u32(smem);
    uint32_t sbw = sbx + WSM_OFF;
    float* srow = (float*)(smem + SROW_OFF);
    float* swsm = (float*)(smem + SWSM_OFF);
    float* cbsm = (float*)(smem + CBSM_OFF);
    float* redb = (float*)(smem + REDB_OFF);

    int tid = threadIdx.x;
    int lane = tid & 31, wid = tid >> 5;
    int warp_m = wid & 3, warp_n = wid >> 2;

    int row0 = blockIdx.x * 128;
    int bt_base = row0 / 49;

    // ---- stage-in x slices (cp.async, group 0) ----
    for (int i = tid; i < 4 * HW_ * 32; i += 256) {
        int s4 = i / (HW_ * 32);
        int r = i - s4 * (HW_ * 32);
        int pos = r >> 5, seg = r & 31;
        int bts = bt_base + s4;
        if (bts < NBT) {
            cp_async16(sbx + (uint32_t)(((s4 * HW_ + pos) * XSTR + seg * 8) * 2),
                       g_xT + ((size_t)bts * HW_ + pos) * C_ + seg * 8);
        }
    }
    cp_commit();
    // zero row 196
    if (tid < 132) ((uint32_t*)(smem + 196 * XSTR * 2))[tid] = 0u;
    for (int i = tid; i < 512; i += 256) { swsm[i] = score_w[i]; cbsm[i] = conv_b[i]; }
    if (tid < 128) srow[tid] = 0.0f;

    // per-lane A-row precompute (two mma-rows per lane: mf = 0/1)
    int srel[2], h0[2], w0[2];
#pragma unroll
    for (int mf = 0; mf < 2; ++mf) {
        int rl = warp_m * 32 + mf * 16 + ((lane >> 3) & 1) * 8 + (lane & 7);
        int rg = row0 + rl;
        int btl = rg / 49;
        int pos = rg - btl * 49;
        srel[mf] = btl - bt_base;
        h0[mf] = pos / 7;
        w0[mf] = pos % 7;
    }
    int akoff = ((lane >> 4) * 8) * 2;                   // A k-col byte offset
    uint32_t brow = sbw + (uint32_t)(((warp_n * 64 + (lane >> 4) * 8 + (lane & 7)) * WSTR
                                      + ((lane >> 3) & 1) * 8) * 2);

    // weight stage loader: stage S -> (nt, tap, c0); 2 threads per d-row
    int wrow = tid >> 1, wseg = tid & 1;
    auto load_w = [&](int S, int buf) {
        int nt = S / 36, s36 = S - nt * 36;
        int tap = s36 >> 2, c0 = (s36 & 3) << 6;
        const __nv_bfloat16* src =
            g_W + ((size_t)(tap * D_ + nt * 128 + wrow)) * C_ + c0 + wseg * 32;
        uint32_t dst = sbw + (uint32_t)(buf * WBUF + (wrow * WSTR + wseg * 32) * 2);
#pragma unroll
        for (int q = 0; q < 4; ++q) cp_async16(dst + q * 16, src + q * 8);
        cp_commit();
    };

    load_w(0, 0);   // group 1

    float acc[2][8][4];
#pragma unroll
    for (int mf = 0; mf < 2; ++mf)
#pragma unroll
        for (int nf = 0; nf < 8; ++nf)
#pragma unroll
            for (int q = 0; q < 4; ++q) acc[mf][nf][q] = 0.0f;

    int nt = 0;
    for (int S = 0; S < 144; ++S) {
        int s36 = S - nt * 36;
        int buf = S & 1;

        if (S < 143) load_w(S + 1, buf ^ 1);
        if (S < 143) asm volatile("cp.async.wait_group 1;\n" ::: "memory");
        else         asm volatile("cp.async.wait_group 0;\n" ::: "memory");
        __syncthreads();

        // per-tap A bases (indirect conv rows; OOB -> zero row 196)
        int tap = s36 >> 2, c0 = (s36 & 3) << 6;
        int dh = tap / 3 - 1, dw = tap % 3 - 1;
        uint32_t abase[2];
#pragma unroll
        for (int mf = 0; mf < 2; ++mf) {
            int ph = h0[mf] + dh, pw = w0[mf] + dw;
            int xr = ((unsigned)ph < 7u && (unsigned)pw < 7u)
                   ? srel[mf] * 49 + ph * 7 + pw : 196;
            abase[mf] = sbx + (uint32_t)((xr * XSTR + c0) * 2) + akoff;
        }
        uint32_t bbase = brow + buf * WBUF;

#pragma unroll
        for (int k16 = 0; k16 < 4; ++k16) {
            int klb = k16 * 32;                           // 16 elems = 32 B
            uint32_t a[2][4];
            ldsm_x4(a[0], abase[0] + klb);
            ldsm_x4(a[1], abase[1] + klb);
#pragma unroll
            for (int nfp = 0; nfp < 4; ++nfp) {
                uint32_t bfrag[4];
                ldsm_x4(bfrag, bbase + (uint32_t)(nfp * 16 * WSTR * 2) + klb);
                mma16816(acc[0][2 * nfp],     a[0], bfrag[0], bfrag[1]);
                mma16816(acc[0][2 * nfp + 1], a[0], bfrag[2], bfrag[3]);
                mma16816(acc[1][2 * nfp],     a[1], bfrag[0], bfrag[1]);
                mma16816(acc[1][2 * nfp + 1], a[1], bfrag[2], bfrag[3]);
            }
        }
        __syncthreads();

        if (s36 == 35) {
            // epilogue for this d-tile: bias + ReLU + score dot -> srow
            int g = lane >> 2, tg = lane & 3;
            int m_base = warp_m * 32;
#pragma unroll
            for (int mf = 0; mf < 2; ++mf) {
                float p0 = 0.f, p1 = 0.f;
#pragma unroll
                for (int nf = 0; nf < 8; ++nf) {
                    int d = nt * 128 + warp_n * 64 + nf * 8 + tg * 2;
                    float cb0 = cbsm[d], cb1 = cbsm[d + 1];
                    float sw0 = swsm[d], sw1 = swsm[d + 1];
                    p0 += sw0 * fmaxf(acc[mf][nf][0] + cb0, 0.f)
                        + sw1 * fmaxf(acc[mf][nf][1] + cb1, 0.f);
                    p1 += sw0 * fmaxf(acc[mf][nf][2] + cb0, 0.f)
                        + sw1 * fmaxf(acc[mf][nf][3] + cb1, 0.f);
                }
                p0 += __shfl_xor_sync(0xffffffff, p0, 1);
                p0 += __shfl_xor_sync(0xffffffff, p0, 2);
                p1 += __shfl_xor_sync(0xffffffff, p1, 1);
                p1 += __shfl_xor_sync(0xffffffff, p1, 2);
                if (tg == 0) {
                    atomicAdd(&srow[m_base + mf * 16 + g], p0);
                    atomicAdd(&srow[m_base + mf * 16 + 8 + g], p1);
                }
#pragma unroll
                for (int nf = 0; nf < 8; ++nf)
#pragma unroll
                    for (int q = 0; q < 4; ++q) acc[mf][nf][q] = 0.0f;
            }
            ++nt;
        }
    }
    __syncthreads();

    // ---- BCE over 128 valid rows, block-reduce, one global atomic ----
    float lsum = 0.0f;
    if (tid < 128) {
        float sl = srow[tid] + __ldg(score_b);
        float y = g_cam[row0 + tid];
        lsum = log1pf(expf(-fabsf(sl)))
             + ((sl > 0.f) ? (1.f - y) * sl : -sl * y);
    }
#pragma unroll
    for (int o = 16; o > 0; o >>= 1) lsum += __shfl_xor_sync(0xffffffff, lsum, o);
    if (lane == 0) redb[wid] = lsum;
    __syncthreads();
    if (tid == 0) {
        float s2 = 0.f;
#pragma unroll
        for (int i = 0; i < 8; ++i) s2 += redb[i];
        atomicAdd(&g_loss, s2);
    }
}

// ---------------- launcher ----------------
extern "C" void kernel_launch(void* const* d_in, const int* in_sizes, int n_in,
                              void* d_out, int out_size) {
    const float* x        = (const float*)d_in[0];
    const float* lv       = (const float*)d_in[1];
    const float* ln       = (const float*)d_in[2];
    const float* wpv      = (const float*)d_in[3];
    const float* wpn      = (const float*)d_in[4];
    const float* conv_w   = (const float*)d_in[5];
    const float* conv_b   = (const float*)d_in[6];
    const float* score_w  = (const float*)d_in[7];
    const float* score_b  = (const float*)d_in[8];
    float* out = (float*)d_out;

    cudaFuncSetAttribute(gemm_kernel, cudaFuncAttributeMaxDynamicSharedMemorySize, SMEM_GEMM);

    prep_w_kernel<<<(9 * D_ * C_ + 255) / 256, 256>>>(conv_w);   // launch 0
    prep_x_kernel<<<NBT, 256>>>(x);                              // launch 1
    cam_kernel<<<B_, 256>>>(x, lv, ln, wpv, wpn);                // launch 2
    init_kernel<<<1, 1>>>();                                     // launch 3
    init_kernel<<<1, 1>>>();                                     // launch 4 (pad so ncu -s5 hits gemm)
    gemm_kernel<<<MROWS / 128, 256, SMEM_GEMM>>>(conv_b, score_w, score_b);  // launch 5
    final_kernel<<<1, 1>>>(out);                                 // launch 6
}